// round 15
// baseline (speedup 1.0000x reference)
#include <cuda_runtime.h>
#include <cuda_fp16.h>
#include <cstdint>
#include <math.h>

// SimCLR InfoNCE + ranking metrics. R15: 256x128 tiles, 512 threads/CTA.
// Single-term fp16 HMMA (sim ~= h16.h16^T, fp32 accum); BK=64, 3-stage
// cp.async ring; uniform col<row gating covers diagonal-crossing tiles.
// Borderline ranks -> flat list -> exact fp32 recheck kernel.

namespace {
constexpr int   N      = 8192;
constexpr int   D      = 512;
constexpr int   HALF   = 4096;
constexpr float TEMP   = 0.07f;
constexpr int   BMR    = 256;                 // tile rows
constexpr int   BNC    = 128;                 // tile cols
constexpr int   BK     = 64;
constexpr int   KSTEPS = 8;                   // 512/64
constexpr int   STAGES = 3;
constexpr int   LDK    = 72;                  // fp16 row stride (144B)
constexpr int   ABUF   = BMR * LDK * 2;       // 36864 B (A per stage)
constexpr int   BBUF   = BNC * LDK * 2;       // 18432 B (B per stage)
constexpr int   STAGEB = ABUF + BBUF;         // 55296
constexpr int   SMEM_DYN = STAGES * STAGEB;   // 165888 -> 1 CTA/SM, 16 warps
constexpr int   NTILES = 32 * 33;             // 1056 (stripe i has 2i+2 tiles)
constexpr float DELTA  = 6e-5f;               // 5 sigma of fp16 dot error
constexpr int   BCAP   = 1 << 21;
constexpr int   REC_BLOCKS = 592;
}

// ---- device scratch ----
__device__ float    g_fn[N * D];
__device__ __half   g_h16[N * D];
__device__ float    g_pos[N];
__device__ float    g_rowS[N];
__device__ int      g_rowC[N];
__device__ uint32_t g_border[BCAP];           // (i<<13)|j
__device__ int      g_nBorder;
__device__ int      g_done;
__device__ double   g_nll;
__device__ int      g_top1;
__device__ int      g_top5;
__device__ unsigned long long g_rank;

__device__ __forceinline__ uint32_t smem_u32(const void* p) {
    uint32_t a;
    asm("{ .reg .u64 t; cvta.to.shared.u64 t, %1; cvt.u32.u64 %0, t; }" : "=r"(a) : "l"(p));
    return a;
}
#define CP16(sa, g) asm volatile("cp.async.cg.shared.global [%0], [%1], 16;" :: "r"(sa), "l"(g))
#define CP_COMMIT() asm volatile("cp.async.commit_group;")
#define CP_WAIT(n)  asm volatile("cp.async.wait_group %0;" :: "n"(n))
#define LDSM4(r0, r1, r2, r3, a)                                             \
    asm volatile("ldmatrix.sync.aligned.m8n8.x4.shared.b16 {%0,%1,%2,%3}, [%4];" \
                 : "=r"(r0), "=r"(r1), "=r"(r2), "=r"(r3) : "r"(a))
#define MMA16816(c, a, b0, b1)                                               \
    asm volatile("mma.sync.aligned.m16n8k16.row.col.f32.f16.f16.f32 "        \
                 "{%0,%1,%2,%3}, {%4,%5,%6,%7}, {%8,%9}, {%0,%1,%2,%3};"     \
                 : "+f"((c)[0]), "+f"((c)[1]), "+f"((c)[2]), "+f"((c)[3])    \
                 : "r"((a)[0]), "r"((a)[1]), "r"((a)[2]), "r"((a)[3]),       \
                   "r"(b0), "r"(b1))

__device__ __forceinline__ void push_border(int i, int j) {
    uint32_t idx = (uint32_t)atomicAdd(&g_nBorder, 1);
    if (idx < (uint32_t)BCAP) g_border[idx] = ((uint32_t)i << 13) | (uint32_t)j;
}

// ---------------- small kernels ----------------
__global__ void k_norm(const float* __restrict__ f1, const float* __restrict__ f2) {
    const int row = blockIdx.x;
    const float* src = (row < HALF) ? (f1 + (size_t)row * D)
                                    : (f2 + (size_t)(row - HALF) * D);
    const int t = threadIdx.x;   // 128 threads x float4
    if (t == 0) {
        g_rowS[row] = 0.f; g_rowC[row] = 0;
        if (row == 0) {
            g_nBorder = 0; g_done = 0;
            g_nll = 0.0; g_top1 = 0; g_top5 = 0; g_rank = 0ull;
        }
    }
    float4 v = reinterpret_cast<const float4*>(src)[t];
    float ss = v.x * v.x + v.y * v.y + v.z * v.z + v.w * v.w;
#pragma unroll
    for (int o = 16; o; o >>= 1) ss += __shfl_xor_sync(0xffffffffu, ss, o);
    __shared__ float ws[4];
    if ((t & 31) == 0) ws[t >> 5] = ss;
    __syncthreads();
    const float inv = 1.0f / fmaxf(sqrtf(ws[0] + ws[1] + ws[2] + ws[3]), 1e-8f);
    float x[4] = { v.x * inv, v.y * inv, v.z * inv, v.w * inv };
    reinterpret_cast<float4*>(g_fn + (size_t)row * D)[t] =
        make_float4(x[0], x[1], x[2], x[3]);
    __half2 h0 = __floats2half2_rn(x[0], x[1]);
    __half2 h1 = __floats2half2_rn(x[2], x[3]);
    reinterpret_cast<__half2*>(g_h16 + (size_t)row * D)[t * 2]     = h0;
    reinterpret_cast<__half2*>(g_h16 + (size_t)row * D)[t * 2 + 1] = h1;
}

__global__ void k_pos() {
    const int row  = blockIdx.x * 8 + (threadIdx.x >> 5);
    const int lane = threadIdx.x & 31;
    const int prow = (row + HALF) & (N - 1);
    const float4* a = reinterpret_cast<const float4*>(g_fn + (size_t)row * D);
    const float4* b = reinterpret_cast<const float4*>(g_fn + (size_t)prow * D);
    float s = 0.f;
#pragma unroll
    for (int q = 0; q < 4; q++) {
        float4 x = a[lane + q * 32], y = b[lane + q * 32];
        s += x.x * y.x + x.y * y.y + x.z * y.z + x.w * y.w;
    }
#pragma unroll
    for (int o = 16; o; o >>= 1) s += __shfl_xor_sync(0xffffffffu, s, o);
    if (lane == 0) g_pos[row] = s;
}

// ---------------- main: 256x128-tile fp16 HMMA GEMM + fused epilogue ----------------
// Stripe i (rows [256i,256i+256)) has col blocks 0..2i+1; tile id start = i(i+1).
__global__ void __launch_bounds__(512, 1) k_main() {
    extern __shared__ __align__(16) char dsm[];

    const int t = blockIdx.x;
    int bi = (int)((sqrtf(4.0f * (float)t + 1.0f) - 1.0f) * 0.5f);
    while ((bi + 1) * (bi + 2) <= t) ++bi;
    while (bi * (bi + 1) > t) --bi;
    const int bj = t - bi * (bi + 1);
    const int rowBase = bi * BMR;
    const int colBase = bj * BNC;

    const int tid  = threadIdx.x;
    const int l    = tid & 31;
    const int wid  = tid >> 5;        // 0..15
    const int warpM = wid & 3;        // 4 -> 64 rows each
    const int warpN = wid >> 2;       // 4 -> 32 cols each
    const float invT = 1.0f / TEMP;

    uint32_t aBufU[STAGES], bBufU[STAGES];
#pragma unroll
    for (int s = 0; s < STAGES; s++) {
        aBufU[s] = smem_u32(dsm + s * STAGEB);
        bBufU[s] = aBufU[s] + ABUF;
    }
    // cp.async chunk maps: A 2048 chunks (4/thread), B 1024 (2/thread)
    uint32_t dstA[4]; int rA[4], qA[4];
#pragma unroll
    for (int i = 0; i < 4; i++) {
        int c = i * 512 + tid;
        rA[i] = c >> 3; qA[i] = c & 7;
        dstA[i] = (uint32_t)(rA[i] * (LDK * 2) + qA[i] * 16);
    }
    uint32_t dstB[2]; int rB[2], qB[2];
#pragma unroll
    for (int i = 0; i < 2; i++) {
        int c = i * 512 + tid;
        rB[i] = c >> 3; qB[i] = c & 7;
        dstB[i] = (uint32_t)(rB[i] * (LDK * 2) + qB[i] * 16);
    }

    const uint32_t aFragOff =
        (uint32_t)(((warpM * 64 + (l & 15)) * LDK + (l >> 4) * 8) * 2);
    const uint32_t bFragOff =
        (uint32_t)(((warpN * 32 + (l & 7) + (l >> 4) * 8) * LDK + ((l >> 3) & 1) * 8) * 2);

    float acc[4][4][4];
#pragma unroll
    for (int mt = 0; mt < 4; mt++)
#pragma unroll
        for (int nt = 0; nt < 4; nt++)
#pragma unroll
            for (int r = 0; r < 4; r++) acc[mt][nt][r] = 0.f;

    auto issue = [&](int g, int b) {
        const int kb = g * BK;
#pragma unroll
        for (int i = 0; i < 4; i++)
            CP16(aBufU[b] + dstA[i],
                 g_h16 + (size_t)(rowBase + rA[i]) * D + kb + qA[i] * 8);
#pragma unroll
        for (int i = 0; i < 2; i++)
            CP16(bBufU[b] + dstB[i],
                 g_h16 + (size_t)(colBase + rB[i]) * D + kb + qB[i] * 8);
    };

    issue(0, 0); CP_COMMIT();
    issue(1, 1); CP_COMMIT();

#pragma unroll
    for (int g = 0; g < KSTEPS; ++g) {
        const int b = g % STAGES;
        CP_WAIT(1);
        __syncthreads();
        if (g + 2 < KSTEPS) issue(g + 2, (g + 2) % STAGES);
        CP_COMMIT();

        const uint32_t ua = aBufU[b], ub = bBufU[b];
        uint32_t bfr[2][2][4];
#pragma unroll
        for (int np = 0; np < 2; np++)
            LDSM4(bfr[0][np][0], bfr[0][np][1], bfr[0][np][2], bfr[0][np][3],
                  ub + bFragOff + (uint32_t)(np * 16 * LDK * 2));
#pragma unroll
        for (int ks = 0; ks < 4; ks++) {
            const int cur = ks & 1;
            if (ks < 3) {
#pragma unroll
                for (int np = 0; np < 2; np++)
                    LDSM4(bfr[cur ^ 1][np][0], bfr[cur ^ 1][np][1],
                          bfr[cur ^ 1][np][2], bfr[cur ^ 1][np][3],
                          ub + bFragOff + (uint32_t)(np * 16 * LDK * 2 + (ks + 1) * 32));
            }
#pragma unroll
            for (int mt = 0; mt < 4; mt++) {
                uint32_t afr[4];
                LDSM4(afr[0], afr[1], afr[2], afr[3],
                      ua + aFragOff + (uint32_t)(mt * 16 * LDK * 2 + ks * 32));
#pragma unroll
                for (int nt = 0; nt < 4; nt++)
                    MMA16816(acc[mt][nt], afr,
                             bfr[cur][nt >> 1][(nt & 1) * 2],
                             bfr[cur][nt >> 1][(nt & 1) * 2 + 1]);
            }
        }
    }

    // ---- fused epilogue (uniform col<row gating; both views always) ----
    float pvR[4][2]; int piR[4][2];
    float pvC[4][2]; int piC[4][2];
    float sR[4][2], sC[4][2];
    int   cR[4][2], cC[4][2];
#pragma unroll
    for (int mt = 0; mt < 4; mt++)
#pragma unroll
        for (int h = 0; h < 2; h++) {
            int row = rowBase + warpM * 64 + mt * 16 + (l >> 2) + h * 8;
            pvR[mt][h] = g_pos[row]; piR[mt][h] = (row + HALF) & (N - 1);
            sR[mt][h] = 0.f; cR[mt][h] = 0;
        }
#pragma unroll
    for (int nt = 0; nt < 4; nt++)
#pragma unroll
        for (int e = 0; e < 2; e++) {
            int col = colBase + warpN * 32 + nt * 8 + (l & 3) * 2 + e;
            pvC[nt][e] = g_pos[col]; piC[nt][e] = (col + HALF) & (N - 1);
            sC[nt][e] = 0.f; cC[nt][e] = 0;
        }

#pragma unroll
    for (int mt = 0; mt < 4; mt++)
#pragma unroll
        for (int nt = 0; nt < 4; nt++)
#pragma unroll
            for (int r = 0; r < 4; r++) {
                const int h = r >> 1, e = r & 1;
                const int row = rowBase + warpM * 64 + mt * 16 + (l >> 2) + h * 8;
                const int col = colBase + warpN * 32 + nt * 8 + (l & 3) * 2 + e;
                if (col < row) {
                    const float sim = acc[mt][nt][r];
                    const float ex  = __expf((sim - 1.0f) * invT);
                    sR[mt][h] += ex;
                    if (col != piR[mt][h]) {
                        float d = sim - pvR[mt][h];
                        if (d > DELTA) cR[mt][h]++;
                        else if (d >= -DELTA) push_border(row, col);
                    }
                    sC[nt][e] += ex;
                    if (row != piC[nt][e]) {
                        float d = sim - pvC[nt][e];
                        if (d > DELTA) cC[nt][e]++;
                        else if (d >= -DELTA) push_border(col, row);
                    }
                }
            }

#pragma unroll
    for (int mt = 0; mt < 4; mt++)
#pragma unroll
        for (int h = 0; h < 2; h++) {
            float s = sR[mt][h]; int c = cR[mt][h];
            s += __shfl_xor_sync(0xffffffffu, s, 1);
            s += __shfl_xor_sync(0xffffffffu, s, 2);
            c += __shfl_xor_sync(0xffffffffu, c, 1);
            c += __shfl_xor_sync(0xffffffffu, c, 2);
            if ((l & 3) == 0) {
                int row = rowBase + warpM * 64 + mt * 16 + (l >> 2) + h * 8;
                atomicAdd(&g_rowS[row], s);
                atomicAdd(&g_rowC[row], c);
            }
        }
#pragma unroll
    for (int nt = 0; nt < 4; nt++)
#pragma unroll
        for (int e = 0; e < 2; e++) {
            float s = sC[nt][e]; int c = cC[nt][e];
            s += __shfl_xor_sync(0xffffffffu, s, 4);
            s += __shfl_xor_sync(0xffffffffu, s, 8);
            s += __shfl_xor_sync(0xffffffffu, s, 16);
            c += __shfl_xor_sync(0xffffffffu, c, 4);
            c += __shfl_xor_sync(0xffffffffu, c, 8);
            c += __shfl_xor_sync(0xffffffffu, c, 16);
            if (l < 4) {
                int col = colBase + warpN * 32 + nt * 8 + (l & 3) * 2 + e;
                atomicAdd(&g_rowS[col], s);
                atomicAdd(&g_rowC[col], c);
            }
        }
}

// Flat exact recheck: one warp per borderline pair (L2-BW floor).
__global__ void k_recheck() {
    const int nWarps = gridDim.x * (blockDim.x >> 5);
    const int w      = blockIdx.x * (blockDim.x >> 5) + (threadIdx.x >> 5);
    const int lane   = threadIdx.x & 31;
    const int cnt    = min(g_nBorder, BCAP);
    for (int e = w; e < cnt; e += nWarps) {
        const uint32_t p = g_border[e];
        const int i = (int)(p >> 13);
        const int j = (int)(p & 8191u);
        const float4* a = reinterpret_cast<const float4*>(g_fn + (size_t)i * D);
        const float4* b = reinterpret_cast<const float4*>(g_fn + (size_t)j * D);
        float s = 0.f;
#pragma unroll
        for (int q = 0; q < 4; q++) {
            float4 x = a[lane + q * 32], y = b[lane + q * 32];
            s = fmaf(x.x, y.x, fmaf(x.y, y.y, fmaf(x.z, y.z, fmaf(x.w, y.w, s))));
        }
#pragma unroll
        for (int o = 16; o; o >>= 1) s += __shfl_xor_sync(0xffffffffu, s, o);
        if (lane == 0 && s > g_pos[i]) atomicAdd(&g_rowC[i], 1);
    }
}

// Per-row stats + global accumulate; last block writes the 4 outputs.
__global__ void k_merge(float* __restrict__ out) {
    const int row = blockIdx.x * 256 + threadIdx.x;
    const float invT = 1.0f / TEMP;
    const float sv = g_rowS[row];
    const int   cv = g_rowC[row];
    const float term = (logf(sv) + invT) - g_pos[row] * invT;
    float wterm = term;
    int wt1 = (cv == 0) ? 1 : 0;
    int wt5 = (cv < 5) ? 1 : 0;
    long long wr = cv;
#pragma unroll
    for (int o = 16; o; o >>= 1) {
        wterm += __shfl_xor_sync(0xffffffffu, wterm, o);
        wt1   += __shfl_xor_sync(0xffffffffu, wt1, o);
        wt5   += __shfl_xor_sync(0xffffffffu, wt5, o);
        wr    += __shfl_xor_sync(0xffffffffu, wr, o);
    }
    __shared__ double s_term[8];
    __shared__ int s_t1[8], s_t5[8];
    __shared__ unsigned long long s_r[8];
    const int lane = threadIdx.x & 31, w = threadIdx.x >> 5;
    if (lane == 0) { s_term[w] = (double)wterm; s_t1[w] = wt1; s_t5[w] = wt5; s_r[w] = (unsigned long long)wr; }
    __syncthreads();
    __shared__ int sIsLast;
    if (threadIdx.x == 0) {
        double a = 0.0; int b = 0, c = 0; unsigned long long d2 = 0ull;
#pragma unroll
        for (int i = 0; i < 8; i++) { a += s_term[i]; b += s_t1[i]; c += s_t5[i]; d2 += s_r[i]; }
        atomicAdd(&g_nll, a);
        atomicAdd(&g_top1, b);
        atomicAdd(&g_top5, c);
        atomicAdd(&g_rank, d2);
        __threadfence();
        sIsLast = (atomicAdd(&g_done, 1) == (int)gridDim.x - 1) ? 1 : 0;
    }
    __syncthreads();
    if (threadIdx.x == 0 && sIsLast) {
        __threadfence();
        out[0] = (float)(g_nll / (double)N);
        out[1] = (float)g_top1 / (float)N;
        out[2] = (float)g_top5 / (float)N;
        out[3] = 1.0f + (float)((double)g_rank / (double)N);
    }
}

extern "C" void kernel_launch(void* const* d_in, const int* in_sizes, int n_in,
                              void* d_out, int out_size) {
    (void)in_sizes; (void)n_in; (void)out_size;
    const float* f1 = (const float*)d_in[0];
    const float* f2 = (const float*)d_in[1];
    float* out = (float*)d_out;

    cudaFuncSetAttribute(k_main, cudaFuncAttributeMaxDynamicSharedMemorySize, SMEM_DYN);

    k_norm<<<N, 128>>>(f1, f2);
    k_pos<<<N / 8, 256>>>();
    k_main<<<NTILES, 512, SMEM_DYN>>>();
    k_recheck<<<REC_BLOCKS, 256>>>();
    k_merge<<<N / 256, 256>>>(out);
}

// round 16
// speedup vs baseline: 1.1059x; 1.1059x over previous
#include <cuda_runtime.h>
#include <cuda_fp16.h>
#include <cstdint>
#include <math.h>

// SimCLR InfoNCE + ranking metrics. R16: R14 (best: 195.3us) with k_pos
// fused into k_norm via pos-symmetry (pos[i] == pos[i+HALF]); one block
// normalizes a mirrored row pair and computes their mutual dot once.
//   k_main: single-term fp16 HMMA GEMM, BK=64, 3-stage cp.async ring,
//   triangular 128x128 tiles, fused exp/rank epilogue, DELTA=6e-5.
//   k_recheck: flat exact-fp32 recheck (L2-BW floor).

namespace {
constexpr int   N      = 8192;
constexpr int   D      = 512;
constexpr int   HALF   = 4096;
constexpr float TEMP   = 0.07f;
constexpr int   BM     = 128;
constexpr int   BK     = 64;
constexpr int   KSTEPS = 8;                   // 512/64
constexpr int   STAGES = 3;
constexpr int   LDK    = 72;                  // fp16 row stride (144B)
constexpr int   BUFB   = BM * LDK * 2;        // 18432 B per matrix per stage
constexpr int   STAGEB = 2 * BUFB;            // 36864
constexpr int   SMEM_DYN = STAGES * STAGEB;   // 110592 -> 2 CTA/SM
constexpr int   NTILES = 64 * 65 / 2;         // 2080
constexpr float DELTA  = 6e-5f;               // 5 sigma of fp16 dot error
constexpr int   BCAP   = 1 << 21;
constexpr int   REC_BLOCKS = 592;
}

// ---- device scratch ----
__device__ float    g_fn[N * D];
__device__ __half   g_h16[N * D];
__device__ float    g_pos[N];
__device__ float    g_rowS[N];
__device__ int      g_rowC[N];
__device__ uint32_t g_border[BCAP];           // (i<<13)|j
__device__ int      g_nBorder;
__device__ int      g_done;
__device__ double   g_nll;
__device__ int      g_top1;
__device__ int      g_top5;
__device__ unsigned long long g_rank;

__device__ __forceinline__ uint32_t smem_u32(const void* p) {
    uint32_t a;
    asm("{ .reg .u64 t; cvta.to.shared.u64 t, %1; cvt.u32.u64 %0, t; }" : "=r"(a) : "l"(p));
    return a;
}
#define CP16(sa, g) asm volatile("cp.async.cg.shared.global [%0], [%1], 16;" :: "r"(sa), "l"(g))
#define CP_COMMIT() asm volatile("cp.async.commit_group;")
#define CP_WAIT(n)  asm volatile("cp.async.wait_group %0;" :: "n"(n))
#define LDSM4(r0, r1, r2, r3, a)                                             \
    asm volatile("ldmatrix.sync.aligned.m8n8.x4.shared.b16 {%0,%1,%2,%3}, [%4];" \
                 : "=r"(r0), "=r"(r1), "=r"(r2), "=r"(r3) : "r"(a))
#define MMA16816(c, a, b0, b1)                                               \
    asm volatile("mma.sync.aligned.m16n8k16.row.col.f32.f16.f16.f32 "        \
                 "{%0,%1,%2,%3}, {%4,%5,%6,%7}, {%8,%9}, {%0,%1,%2,%3};"     \
                 : "+f"((c)[0]), "+f"((c)[1]), "+f"((c)[2]), "+f"((c)[3])    \
                 : "r"((a)[0]), "r"((a)[1]), "r"((a)[2]), "r"((a)[3]),       \
                   "r"(b0), "r"(b1))

__device__ __forceinline__ void push_border(int i, int j) {
    uint32_t idx = (uint32_t)atomicAdd(&g_nBorder, 1);
    if (idx < (uint32_t)BCAP) g_border[idx] = ((uint32_t)i << 13) | (uint32_t)j;
}

// ---------------- fused normalize + positive-pair dot ----------------
// Block b handles rows i=b and j=b+HALF (the positive pair). Group 0
// (threads 0-127) owns row i, group 1 owns row j. After normalizing,
// both normalized rows sit in smem; one dot gives pos[i] == pos[j].
__global__ void __launch_bounds__(256) k_normpos(
    const float* __restrict__ f1, const float* __restrict__ f2
) {
    const int i   = blockIdx.x;          // 0..HALF-1
    const int grp = threadIdx.x >> 7;    // 0: row i (from f1), 1: row i+HALF (f2)
    const int t   = threadIdx.x & 127;   // float4 index within the row
    const int row = grp ? (i + HALF) : i;
    const float* src = grp ? (f2 + (size_t)i * D) : (f1 + (size_t)i * D);

    if (t == 0) {
        g_rowS[row] = 0.f; g_rowC[row] = 0;
        if (threadIdx.x == 0 && i == 0) {
            g_nBorder = 0; g_done = 0;
            g_nll = 0.0; g_top1 = 0; g_top5 = 0; g_rank = 0ull;
        }
    }

    __shared__ __align__(16) float xbuf[2][D];
    __shared__ float ws[2][4];
    __shared__ float sdot[8];

    float4 v = reinterpret_cast<const float4*>(src)[t];
    float ss = v.x * v.x + v.y * v.y + v.z * v.z + v.w * v.w;
#pragma unroll
    for (int o = 16; o; o >>= 1) ss += __shfl_xor_sync(0xffffffffu, ss, o);
    if ((t & 31) == 0) ws[grp][t >> 5] = ss;
    __syncthreads();
    const float inv = 1.0f / fmaxf(
        sqrtf(ws[grp][0] + ws[grp][1] + ws[grp][2] + ws[grp][3]), 1e-8f);
    float4 x = make_float4(v.x * inv, v.y * inv, v.z * inv, v.w * inv);
    reinterpret_cast<float4*>(g_fn + (size_t)row * D)[t] = x;
    reinterpret_cast<float4*>(&xbuf[grp][0])[t] = x;
    __half2 h0 = __floats2half2_rn(x.x, x.y);
    __half2 h1 = __floats2half2_rn(x.z, x.w);
    reinterpret_cast<__half2*>(g_h16 + (size_t)row * D)[t * 2]     = h0;
    reinterpret_cast<__half2*>(g_h16 + (size_t)row * D)[t * 2 + 1] = h1;
    __syncthreads();

    // mutual dot: all 256 threads cover 512 elems as float4 pairs (2/thread? no:
    // 128 float4 slots; group 0 threads take slot t, group 1 idle-contribute 0)
    float p = 0.f;
    if (grp == 0) {
        float4 a4 = reinterpret_cast<const float4*>(&xbuf[0][0])[t];
        float4 b4 = reinterpret_cast<const float4*>(&xbuf[1][0])[t];
        p = a4.x * b4.x + a4.y * b4.y + a4.z * b4.z + a4.w * b4.w;
    }
#pragma unroll
    for (int o = 16; o; o >>= 1) p += __shfl_xor_sync(0xffffffffu, p, o);
    if ((threadIdx.x & 31) == 0) sdot[threadIdx.x >> 5] = p;
    __syncthreads();
    if (threadIdx.x == 0) {
        const float pos = sdot[0] + sdot[1] + sdot[2] + sdot[3];
        g_pos[i] = pos;
        g_pos[i + HALF] = pos;
    }
}

// ---------------- main: triangular-tile fp16 HMMA GEMM + fused epilogue ----------------
__global__ void __launch_bounds__(256, 2) k_main() {
    extern __shared__ __align__(16) char dsm[];

    const int t = blockIdx.x;
    int bi = (int)((sqrtf(8.0f * (float)t + 1.0f) - 1.0f) * 0.5f);
    while ((bi + 1) * (bi + 2) / 2 <= t) ++bi;
    while (bi * (bi + 1) / 2 > t) --bi;
    const int bj = t - bi * (bi + 1) / 2;
    const bool offd = (bi != bj);
    const int rowBase = bi * BM;
    const int colBase = bj * BM;

    const int tid  = threadIdx.x;
    const int l    = tid & 31;
    const int wid  = tid >> 5;
    const int warpM = wid & 1;
    const int warpN = wid >> 1;
    const float invT = 1.0f / TEMP;

    uint32_t aBufU[STAGES], bBufU[STAGES];
#pragma unroll
    for (int s = 0; s < STAGES; s++) {
        aBufU[s] = smem_u32(dsm + s * STAGEB);
        bBufU[s] = aBufU[s] + BUFB;
    }
    uint32_t dstOff[4];
    int gRow[4], gQ[4];
#pragma unroll
    for (int i = 0; i < 4; i++) {
        int c = i * 256 + tid;
        gRow[i] = c >> 3; gQ[i] = c & 7;
        dstOff[i] = (uint32_t)(gRow[i] * (LDK * 2) + gQ[i] * 16);
    }

    const uint32_t aFragOff =
        (uint32_t)(((warpM * 64 + (l & 15)) * LDK + (l >> 4) * 8) * 2);
    const uint32_t bFragOff =
        (uint32_t)(((warpN * 32 + (l & 7) + (l >> 4) * 8) * LDK + ((l >> 3) & 1) * 8) * 2);

    float acc[4][4][4];
#pragma unroll
    for (int mt = 0; mt < 4; mt++)
#pragma unroll
        for (int nt = 0; nt < 4; nt++)
#pragma unroll
            for (int r = 0; r < 4; r++) acc[mt][nt][r] = 0.f;

    auto issue = [&](int g, int b) {
        const int kb = g * BK;
#pragma unroll
        for (int i = 0; i < 4; i++) {
            CP16(aBufU[b] + dstOff[i],
                 g_h16 + (size_t)(rowBase + gRow[i]) * D + kb + gQ[i] * 8);
            CP16(bBufU[b] + dstOff[i],
                 g_h16 + (size_t)(colBase + gRow[i]) * D + kb + gQ[i] * 8);
        }
    };

    issue(0, 0); CP_COMMIT();
    issue(1, 1); CP_COMMIT();

#pragma unroll
    for (int g = 0; g < KSTEPS; ++g) {
        const int b = g % STAGES;
        CP_WAIT(1);
        __syncthreads();
        if (g + 2 < KSTEPS) issue(g + 2, (g + 2) % STAGES);
        CP_COMMIT();

        const uint32_t ua = aBufU[b], ub = bBufU[b];
        uint32_t bfr[2][2][4];
#pragma unroll
        for (int np = 0; np < 2; np++)
            LDSM4(bfr[0][np][0], bfr[0][np][1], bfr[0][np][2], bfr[0][np][3],
                  ub + bFragOff + (uint32_t)(np * 16 * LDK * 2));
#pragma unroll
        for (int ks = 0; ks < 4; ks++) {
            const int cur = ks & 1;
            if (ks < 3) {
#pragma unroll
                for (int np = 0; np < 2; np++)
                    LDSM4(bfr[cur ^ 1][np][0], bfr[cur ^ 1][np][1],
                          bfr[cur ^ 1][np][2], bfr[cur ^ 1][np][3],
                          ub + bFragOff + (uint32_t)(np * 16 * LDK * 2 + (ks + 1) * 32));
            }
#pragma unroll
            for (int mt = 0; mt < 4; mt++) {
                uint32_t afr[4];
                LDSM4(afr[0], afr[1], afr[2], afr[3],
                      ua + aFragOff + (uint32_t)(mt * 16 * LDK * 2 + ks * 32));
#pragma unroll
                for (int nt = 0; nt < 4; nt++)
                    MMA16816(acc[mt][nt], afr,
                             bfr[cur][nt >> 1][(nt & 1) * 2],
                             bfr[cur][nt >> 1][(nt & 1) * 2 + 1]);
            }
        }
    }

    // ---- fused epilogue ----
    float pvR[4][2]; int piR[4][2];
    float pvC[4][2]; int piC[4][2];
    float sR[4][2], sC[4][2];
    int   cR[4][2], cC[4][2];
#pragma unroll
    for (int mt = 0; mt < 4; mt++)
#pragma unroll
        for (int h = 0; h < 2; h++) {
            int row = rowBase + warpM * 64 + mt * 16 + (l >> 2) + h * 8;
            pvR[mt][h] = g_pos[row]; piR[mt][h] = (row + HALF) & (N - 1);
            sR[mt][h] = 0.f; cR[mt][h] = 0;
        }
#pragma unroll
    for (int nt = 0; nt < 4; nt++)
#pragma unroll
        for (int e = 0; e < 2; e++) {
            int col = colBase + warpN * 32 + nt * 8 + (l & 3) * 2 + e;
            pvC[nt][e] = g_pos[col]; piC[nt][e] = (col + HALF) & (N - 1);
            sC[nt][e] = 0.f; cC[nt][e] = 0;
        }

#pragma unroll
    for (int mt = 0; mt < 4; mt++)
#pragma unroll
        for (int nt = 0; nt < 4; nt++)
#pragma unroll
            for (int r = 0; r < 4; r++) {
                const int h = r >> 1, e = r & 1;
                const int row = rowBase + warpM * 64 + mt * 16 + (l >> 2) + h * 8;
                const int col = colBase + warpN * 32 + nt * 8 + (l & 3) * 2 + e;
                const float sim = acc[mt][nt][r];
                const float ex  = __expf((sim - 1.0f) * invT);
                if (col != row) {
                    sR[mt][h] += ex;
                    if (col != piR[mt][h]) {
                        float d = sim - pvR[mt][h];
                        if (d > DELTA) cR[mt][h]++;
                        else if (d >= -DELTA) push_border(row, col);
                    }
                }
                if (offd) {
                    sC[nt][e] += ex;
                    if (row != piC[nt][e]) {
                        float d = sim - pvC[nt][e];
                        if (d > DELTA) cC[nt][e]++;
                        else if (d >= -DELTA) push_border(col, row);
                    }
                }
            }

#pragma unroll
    for (int mt = 0; mt < 4; mt++)
#pragma unroll
        for (int h = 0; h < 2; h++) {
            float s = sR[mt][h]; int c = cR[mt][h];
            s += __shfl_xor_sync(0xffffffffu, s, 1);
            s += __shfl_xor_sync(0xffffffffu, s, 2);
            c += __shfl_xor_sync(0xffffffffu, c, 1);
            c += __shfl_xor_sync(0xffffffffu, c, 2);
            if ((l & 3) == 0) {
                int row = rowBase + warpM * 64 + mt * 16 + (l >> 2) + h * 8;
                atomicAdd(&g_rowS[row], s);
                atomicAdd(&g_rowC[row], c);
            }
        }
    if (offd) {
#pragma unroll
        for (int nt = 0; nt < 4; nt++)
#pragma unroll
            for (int e = 0; e < 2; e++) {
                float s = sC[nt][e]; int c = cC[nt][e];
                s += __shfl_xor_sync(0xffffffffu, s, 4);
                s += __shfl_xor_sync(0xffffffffu, s, 8);
                s += __shfl_xor_sync(0xffffffffu, s, 16);
                c += __shfl_xor_sync(0xffffffffu, c, 4);
                c += __shfl_xor_sync(0xffffffffu, c, 8);
                c += __shfl_xor_sync(0xffffffffu, c, 16);
                if (l < 4) {
                    int col = colBase + warpN * 32 + nt * 8 + (l & 3) * 2 + e;
                    atomicAdd(&g_rowS[col], s);
                    atomicAdd(&g_rowC[col], c);
                }
            }
    }
}

// Flat exact recheck: one warp per borderline pair (L2-BW floor).
__global__ void k_recheck() {
    const int nWarps = gridDim.x * (blockDim.x >> 5);
    const int w      = blockIdx.x * (blockDim.x >> 5) + (threadIdx.x >> 5);
    const int lane   = threadIdx.x & 31;
    const int cnt    = min(g_nBorder, BCAP);
    for (int e = w; e < cnt; e += nWarps) {
        const uint32_t p = g_border[e];
        const int i = (int)(p >> 13);
        const int j = (int)(p & 8191u);
        const float4* a = reinterpret_cast<const float4*>(g_fn + (size_t)i * D);
        const float4* b = reinterpret_cast<const float4*>(g_fn + (size_t)j * D);
        float s = 0.f;
#pragma unroll
        for (int q = 0; q < 4; q++) {
            float4 x = a[lane + q * 32], y = b[lane + q * 32];
            s = fmaf(x.x, y.x, fmaf(x.y, y.y, fmaf(x.z, y.z, fmaf(x.w, y.w, s))));
        }
#pragma unroll
        for (int o = 16; o; o >>= 1) s += __shfl_xor_sync(0xffffffffu, s, o);
        if (lane == 0 && s > g_pos[i]) atomicAdd(&g_rowC[i], 1);
    }
}

// Per-row stats + global accumulate; last block writes the 4 outputs.
__global__ void k_merge(float* __restrict__ out) {
    const int row = blockIdx.x * 256 + threadIdx.x;
    const float invT = 1.0f / TEMP;
    const float sv = g_rowS[row];
    const int   cv = g_rowC[row];
    const float term = (logf(sv) + invT) - g_pos[row] * invT;
    float wterm = term;
    int wt1 = (cv == 0) ? 1 : 0;
    int wt5 = (cv < 5) ? 1 : 0;
    long long wr = cv;
#pragma unroll
    for (int o = 16; o; o >>= 1) {
        wterm += __shfl_xor_sync(0xffffffffu, wterm, o);
        wt1   += __shfl_xor_sync(0xffffffffu, wt1, o);
        wt5   += __shfl_xor_sync(0xffffffffu, wt5, o);
        wr    += __shfl_xor_sync(0xffffffffu, wr, o);
    }
    __shared__ double s_term[8];
    __shared__ int s_t1[8], s_t5[8];
    __shared__ unsigned long long s_r[8];
    const int lane = threadIdx.x & 31, w = threadIdx.x >> 5;
    if (lane == 0) { s_term[w] = (double)wterm; s_t1[w] = wt1; s_t5[w] = wt5; s_r[w] = (unsigned long long)wr; }
    __syncthreads();
    __shared__ int sIsLast;
    if (threadIdx.x == 0) {
        double a = 0.0; int b = 0, c = 0; unsigned long long d2 = 0ull;
#pragma unroll
        for (int i = 0; i < 8; i++) { a += s_term[i]; b += s_t1[i]; c += s_t5[i]; d2 += s_r[i]; }
        atomicAdd(&g_nll, a);
        atomicAdd(&g_top1, b);
        atomicAdd(&g_top5, c);
        atomicAdd(&g_rank, d2);
        __threadfence();
        sIsLast = (atomicAdd(&g_done, 1) == (int)gridDim.x - 1) ? 1 : 0;
    }
    __syncthreads();
    if (threadIdx.x == 0 && sIsLast) {
        __threadfence();
        out[0] = (float)(g_nll / (double)N);
        out[1] = (float)g_top1 / (float)N;
        out[2] = (float)g_top5 / (float)N;
        out[3] = 1.0f + (float)((double)g_rank / (double)N);
    }
}

extern "C" void kernel_launch(void* const* d_in, const int* in_sizes, int n_in,
                              void* d_out, int out_size) {
    (void)in_sizes; (void)n_in; (void)out_size;
    const float* f1 = (const float*)d_in[0];
    const float* f2 = (const float*)d_in[1];
    float* out = (float*)d_out;

    cudaFuncSetAttribute(k_main, cudaFuncAttributeMaxDynamicSharedMemorySize, SMEM_DYN);

    k_normpos<<<HALF, 256>>>(f1, f2);
    k_main<<<NTILES, 256, SMEM_DYN>>>();
    k_recheck<<<REC_BLOCKS, 256>>>();
    k_merge<<<N / 256, 256>>>(out);
}